// round 12
// baseline (speedup 1.0000x reference)
#include <cuda_runtime.h>
#include <cuda_fp16.h>
#include <cstdint>

// Second-order conv2d as fused fp16 implicit GEMM on mma.sync (HMMA).
// Warp-specialized: 8 consumer warps (128 oc x 256 pos CTA tile, 64x64 each)
// run only ldsm+MMA; 2 producer warps run featgen + cp.async W + tap loads.
// W and F double-buffered, one bar.sync per channel-pair.

#define NB 8
#define NC 64
#define NOC 128
#define IH 96
#define IW 96
#define XCH (IH * IW)
#define NTW 3                   // 96 / 32
#define TILES_PER_IMG 36        // 12 x 3
#define NPAIR 32
#define WROWB 240               // bytes per W oc-row (120 fp16)
#define FROWB 240               // bytes per F pos-row (120 fp16: 112 k + 8 pad)
#define NTHREADS 320            // 8 consumer warps + 2 producer warps

// ---- SMEM layout (bytes) ----
#define SM_W0 0                          // 128*240 = 30720
#define SM_W1 30720
#define SM_F0 61440                      // 256*240 = 61440
#define SM_F1 122880
#define SM_TOTAL 184320

#define W_TILE_B 30720
#define W_CHUNKS (W_TILE_B / 16)         // 1920 -> 30 per producer thread
#define WROW 120

// Pre-padded fp16 weights: [pair][128 oc][120], cols 108..119 zero.
__device__ __align__(16) __half g_W[NPAIR * NOC * WROW];

// ---------------- helpers ----------------
__device__ __forceinline__ uint32_t smem_u32(const void* p) {
    uint32_t a;
    asm("{ .reg .u64 t; cvta.to.shared.u64 t, %1; cvt.u32.u64 %0, t; }" : "=r"(a) : "l"(p));
    return a;
}

__device__ __forceinline__ void barrier_all() {
    asm volatile("bar.sync 0, %0;" :: "n"(NTHREADS) : "memory");
}

__device__ __forceinline__ void ldsm_x4(uint32_t* r, uint32_t addr) {
    asm volatile("ldmatrix.sync.aligned.m8n8.x4.shared.b16 {%0,%1,%2,%3}, [%4];"
                 : "=r"(r[0]), "=r"(r[1]), "=r"(r[2]), "=r"(r[3]) : "r"(addr));
}

__device__ __forceinline__ void mma16816(float* d, const uint32_t* a, const uint32_t* b) {
    asm volatile(
        "mma.sync.aligned.m16n8k16.row.col.f32.f16.f16.f32 "
        "{%0,%1,%2,%3}, {%4,%5,%6,%7}, {%8,%9}, {%0,%1,%2,%3};"
        : "+f"(d[0]), "+f"(d[1]), "+f"(d[2]), "+f"(d[3])
        : "r"(a[0]), "r"(a[1]), "r"(a[2]), "r"(a[3]), "r"(b[0]), "r"(b[1]));
}

__device__ __forceinline__ void cpasync16(uint32_t dst, const void* src) {
    asm volatile("cp.async.cg.shared.global [%0], [%1], 16;" :: "r"(dst), "l"(src));
}

// feature i (0..53) of one channel's 9 taps; folds to one mul under full unroll
__device__ __forceinline__ float featval(const float* t9, int i) {
    if (i < 9)  return t9[i];
    if (i < 18) return t9[i - 9] * t9[i - 9];
    int r = i - 18, off, base;
    if      (r <  8) { off = 1; base = r; }
    else if (r < 15) { off = 2; base = r - 8; }
    else if (r < 21) { off = 3; base = r - 15; }
    else if (r < 26) { off = 4; base = r - 21; }
    else if (r < 30) { off = 5; base = r - 26; }
    else if (r < 33) { off = 6; base = r - 30; }
    else if (r < 35) { off = 7; base = r - 33; }
    else             { off = 8; base = 0; }
    return t9[base] * t9[base + off];
}

// write one position's 112 k-values (108 features + 4 zeros) as 14 x 16B
__device__ __forceinline__ void featgen_row(uint32_t dst, const float* t9a, const float* t9b) {
#pragma unroll
    for (int v = 0; v < 14; ++v) {
        uint32_t qs[4];
#pragma unroll
        for (int h = 0; h < 4; ++h) {
            int i0 = v * 8 + h * 2, i1 = i0 + 1;
            float f0 = (i0 < 108) ? ((i0 < 54) ? featval(t9a, i0) : featval(t9b, i0 - 54)) : 0.f;
            float f1 = (i1 < 108) ? ((i1 < 54) ? featval(t9a, i1) : featval(t9b, i1 - 54)) : 0.f;
            __half2 hh = __floats2half2_rn(f0, f1);
            qs[h] = *(uint32_t*)&hh;
        }
        asm volatile("st.shared.v4.b32 [%0], {%1,%2,%3,%4};"
                     :: "r"(dst + v * 16), "r"(qs[0]), "r"(qs[1]), "r"(qs[2]), "r"(qs[3])
                     : "memory");
    }
}

// ---------------- weight prep: pad + convert ----------------
__global__ void prep_w(const float* __restrict__ w) {
    int idx = blockIdx.x * 256 + threadIdx.x;
    if (idx >= NPAIR * NOC * WROW) return;
    int k = idx % WROW;
    int o = (idx / WROW) % NOC;
    int p = idx / (WROW * NOC);
    float v = 0.0f;
    if (k < 108) {
        int c = 2 * p + k / 54, f = k % 54;
        v = w[(o * NC + c) * 54 + f];
    }
    g_W[idx] = __float2half(v);
}

// ---------------- main fused kernel ----------------
__global__ void __launch_bounds__(NTHREADS, 1)
soc_fp16_kernel(const float* __restrict__ x, float* __restrict__ out) {
    extern __shared__ char smc[];
    const uint32_t smb = smem_u32(smc);
    const int tid  = threadIdx.x;
    const int wid  = tid >> 5;
    const int lane = tid & 31;

    const int bx = blockIdx.x;
    const int bb = bx / TILES_PER_IMG;
    const int t  = bx - bb * TILES_PER_IMG;
    const int th = t / NTW;
    const int h0 = th * 8;
    const int w0 = (t - th * NTW) * 32;
    const float* xb = x + (size_t)bb * NC * XCH;

    if (wid < 8) {
        // ================= CONSUMER: pure ldsm + MMA =================
        const int m0 = (wid & 1) * 64;
        const int n0 = (wid >> 1) * 64;

        const uint32_t aoff = (uint32_t)((m0 + (lane & 15)) * WROWB + (lane >> 4) * 16);
        // B (non-trans x4): lanes 0-7 m0(pos+0..7,k+0), 8-15 m1(pos,k+16),
        //                   16-23 m2(pos+8,k+0), 24-31 m3(pos+8,k+16)
        const uint32_t boff = (uint32_t)(n0 * FROWB + ((lane >> 4) & 1) * 8 * FROWB +
                                         ((lane >> 3) & 1) * 16 + (lane & 7) * FROWB);

        float acc[4][8][4];
#pragma unroll
        for (int i = 0; i < 4; ++i)
#pragma unroll
            for (int j = 0; j < 8; ++j)
#pragma unroll
                for (int k = 0; k < 4; ++k) acc[i][j][k] = 0.0f;

        barrier_all();   // wait for W(0) + F(0) from producers

        for (int p = 0; p < NPAIR; ++p) {
            const uint32_t wcur = smb + ((p & 1) ? SM_W1 : SM_W0);
            const uint32_t fcur = smb + ((p & 1) ? SM_F1 : SM_F0);
#pragma unroll
            for (int ks = 0; ks < 7; ++ks) {
                uint32_t ah[4][4], bq[4][4];
#pragma unroll
                for (int mt = 0; mt < 4; ++mt)
                    ldsm_x4(ah[mt], wcur + aoff + (uint32_t)(mt * 16 * WROWB + ks * 32));
#pragma unroll
                for (int q = 0; q < 4; ++q)
                    ldsm_x4(bq[q], fcur + boff + (uint32_t)(q * 16 * FROWB + ks * 32));
#pragma unroll
                for (int mt = 0; mt < 4; ++mt)
#pragma unroll
                    for (int q = 0; q < 4; ++q) {
                        mma16816(acc[mt][2 * q],     ah[mt], &bq[q][0]);
                        mma16816(acc[mt][2 * q + 1], ah[mt], &bq[q][2]);
                    }
            }
            if (p < NPAIR - 1) barrier_all();
        }

        // epilogue: direct register -> global float2 stores
        const int l4 = lane >> 2;
        const int l2 = (lane & 3) * 2;
#pragma unroll
        for (int mt = 0; mt < 4; ++mt) {
#pragma unroll
            for (int nt = 0; nt < 8; ++nt) {
                int oc = m0 + 16 * mt + l4;
                int pp = n0 + 8 * nt + l2;
                int hh = h0 + (pp >> 5);
                int ww = w0 + (pp & 31);
                float* p0 = out + (((size_t)(bb * NOC + oc) * IH + hh) * IW + ww);
                *(float2*)p0 = make_float2(acc[mt][nt][0], acc[mt][nt][1]);
                *(float2*)(p0 + (size_t)8 * IH * IW) =
                    make_float2(acc[mt][nt][2], acc[mt][nt][3]);  // oc + 8
            }
        }
    } else {
        // ================= PRODUCER: featgen + W copy + taps =================
        const int ptid = tid - 256;      // 0..63, owns positions ptid + 64*j
        int offv[4][9];
#pragma unroll
        for (int j = 0; j < 4; ++j) {
            int pos = ptid + 64 * j;
            int prr = pos >> 5, pcc = pos & 31;
#pragma unroll
            for (int kh = 0; kh < 3; ++kh)
#pragma unroll
                for (int kw = 0; kw < 3; ++kw) {
                    int gh = h0 + prr - 1 + kh;
                    int gw = w0 + pcc - 1 + kw;
                    offv[j][kh * 3 + kw] =
                        ((unsigned)gh < IH && (unsigned)gw < IW) ? gh * IW + gw : -1;
                }
        }

        float t9a[4][9], t9b[4][9];

        // prologue: W(0) copy + featgen pair 0 + taps pair 1
        {
            const char* src = (const char*)g_W;
#pragma unroll
            for (int i = 0; i < 30; ++i)
                cpasync16(smb + SM_W0 + (ptid + i * 64) * 16, src + (ptid + i * 64) * 16);
            asm volatile("cp.async.commit_group;");
        }
#pragma unroll
        for (int j = 0; j < 4; ++j)
#pragma unroll
            for (int k = 0; k < 9; ++k) {
                int o = offv[j][k];
                t9a[j][k] = (o >= 0) ? xb[o] : 0.0f;
                t9b[j][k] = (o >= 0) ? xb[XCH + o] : 0.0f;
            }
#pragma unroll
        for (int j = 0; j < 4; ++j)
            featgen_row(smb + SM_F0 + (uint32_t)((ptid + 64 * j) * FROWB),
                        t9a[j], t9b[j]);
#pragma unroll
        for (int j = 0; j < 4; ++j)
#pragma unroll
            for (int k = 0; k < 9; ++k) {
                int o = offv[j][k];
                t9a[j][k] = (o >= 0) ? xb[2 * XCH + o] : 0.0f;
                t9b[j][k] = (o >= 0) ? xb[3 * XCH + o] : 0.0f;
            }
        asm volatile("cp.async.wait_group 0;" ::: "memory");
        barrier_all();

        for (int p = 0; p < NPAIR; ++p) {
            if (p < NPAIR - 1) {
                // stage W(p+1)
                const char* src = (const char*)g_W + (size_t)(p + 1) * W_TILE_B;
                const uint32_t dst = smb + ((p & 1) ? SM_W0 : SM_W1);
#pragma unroll
                for (int i = 0; i < 30; ++i)
                    cpasync16(dst + (ptid + i * 64) * 16, src + (ptid + i * 64) * 16);
                asm volatile("cp.async.commit_group;");

                // featgen pair p+1 into the other F buffer
                const uint32_t fnxt = smb + ((p & 1) ? SM_F0 : SM_F1);
#pragma unroll
                for (int j = 0; j < 4; ++j)
                    featgen_row(fnxt + (uint32_t)((ptid + 64 * j) * FROWB),
                                t9a[j], t9b[j]);

                // taps for pair p+2
                if (p + 2 < NPAIR) {
                    const float* xc = xb + (size_t)(2 * (p + 2)) * XCH;
#pragma unroll
                    for (int j = 0; j < 4; ++j)
#pragma unroll
                        for (int k = 0; k < 9; ++k) {
                            int o = offv[j][k];
                            t9a[j][k] = (o >= 0) ? xc[o] : 0.0f;
                            t9b[j][k] = (o >= 0) ? xc[XCH + o] : 0.0f;
                        }
                }
                asm volatile("cp.async.wait_group 0;" ::: "memory");
            }
            if (p < NPAIR - 1) barrier_all();
        }
    }
}

extern "C" void kernel_launch(void* const* d_in, const int* in_sizes, int n_in,
                              void* d_out, int out_size) {
    const float* x = (const float*)d_in[0];  // [8, 64, 96, 96]
    const float* w = (const float*)d_in[1];  // [128, 64, 54, 1]
    float* out = (float*)d_out;              // [8, 128, 96, 96]
    (void)in_sizes; (void)n_in; (void)out_size;

    cudaFuncSetAttribute(soc_fp16_kernel,
                         cudaFuncAttributeMaxDynamicSharedMemorySize, SM_TOTAL);

    prep_w<<<(NPAIR * NOC * WROW + 255) / 256, 256>>>(w);
    soc_fp16_kernel<<<NB * TILES_PER_IMG, NTHREADS, SM_TOTAL>>>(x, out);
}

// round 13
// speedup vs baseline: 1.1927x; 1.1927x over previous
#include <cuda_runtime.h>
#include <cuda_fp16.h>
#include <cstdint>

// Second-order conv2d as fused fp16 implicit GEMM on mma.sync (HMMA).
// R7 skeleton: CTA 128 oc x 256 pos, 8 warps (64x64), occ 1, W+F double-
// buffered, one __syncthreads per channel-pair, F stored [pos][k].
// NEW: k-interleaved layout (k=2i -> feature i of channel a, k=2i+1 -> of
// channel b) so featgen is pure half2 math: 9 packs + 45 HMUL2 + 14 st.v4.

#define NB 8
#define NC 64
#define NOC 128
#define IH 96
#define IW 96
#define XCH (IH * IW)
#define NTW 3                   // 96 / 32
#define TILES_PER_IMG 36        // 12 x 3
#define NPAIR 32
#define WROWB 240               // bytes per W oc-row (120 fp16; 112 k + 8 pad)
#define FROWB 240               // bytes per F pos-row (120 fp16; 112 k + 8 pad)

// ---- SMEM layout (bytes) ----
#define SM_W0 0                          // 128*240 = 30720
#define SM_W1 30720
#define SM_F0 61440                      // 256*240 = 61440
#define SM_F1 122880
#define SM_TOTAL 184320

#define W_TILE_B 30720
#define W_CHUNKS (W_TILE_B / 16)         // 1920
#define WROW 120

// Pre-padded fp16 weights, k-interleaved: [pair][128 oc][120].
__device__ __align__(16) __half g_W[NPAIR * NOC * WROW];

// ---------------- helpers ----------------
__device__ __forceinline__ uint32_t smem_u32(const void* p) {
    uint32_t a;
    asm("{ .reg .u64 t; cvta.to.shared.u64 t, %1; cvt.u32.u64 %0, t; }" : "=r"(a) : "l"(p));
    return a;
}

__device__ __forceinline__ void ldsm_x4(uint32_t* r, uint32_t addr) {
    asm volatile("ldmatrix.sync.aligned.m8n8.x4.shared.b16 {%0,%1,%2,%3}, [%4];"
                 : "=r"(r[0]), "=r"(r[1]), "=r"(r[2]), "=r"(r[3]) : "r"(addr));
}

__device__ __forceinline__ void mma16816(float* d, const uint32_t* a, const uint32_t* b) {
    asm volatile(
        "mma.sync.aligned.m16n8k16.row.col.f32.f16.f16.f32 "
        "{%0,%1,%2,%3}, {%4,%5,%6,%7}, {%8,%9}, {%0,%1,%2,%3};"
        : "+f"(d[0]), "+f"(d[1]), "+f"(d[2]), "+f"(d[3])
        : "r"(a[0]), "r"(a[1]), "r"(a[2]), "r"(a[3]), "r"(b[0]), "r"(b[1]));
}

__device__ __forceinline__ void cpasync16(uint32_t dst, const void* src) {
    asm volatile("cp.async.cg.shared.global [%0], [%1], 16;" :: "r"(dst), "l"(src));
}

// cross-product index pair for cross feature r (0..35): (base, base+off)
__device__ __forceinline__ void cross_idx(int r, int& base, int& off) {
    if      (r <  8) { off = 1; base = r; }
    else if (r < 15) { off = 2; base = r - 8; }
    else if (r < 21) { off = 3; base = r - 15; }
    else if (r < 26) { off = 4; base = r - 21; }
    else if (r < 30) { off = 5; base = r - 26; }
    else if (r < 33) { off = 6; base = r - 30; }
    else if (r < 35) { off = 7; base = r - 33; }
    else             { off = 8; base = 0; }
}

// feature i (0..55, both channels packed in half2); folds under full unroll
__device__ __forceinline__ __half2 featval_h2(const __half2* t9, int i) {
    if (i < 9)  return t9[i];
    if (i < 18) return __hmul2(t9[i - 9], t9[i - 9]);
    if (i < 54) {
        int base, off;
        cross_idx(i - 18, base, off);
        return __hmul2(t9[base], t9[base + off]);
    }
    return __floats2half2_rn(0.f, 0.f);
}

// write one position's 112 k-values (56 half2, k-interleaved) as 14 x 16B
__device__ __forceinline__ void featgen_row(uint32_t dst, const __half2* t9) {
#pragma unroll
    for (int v = 0; v < 14; ++v) {
        uint32_t qs[4];
#pragma unroll
        for (int h = 0; h < 4; ++h) {
            __half2 r = featval_h2(t9, v * 4 + h);
            qs[h] = *(uint32_t*)&r;
        }
        asm volatile("st.shared.v4.b32 [%0], {%1,%2,%3,%4};"
                     :: "r"(dst + v * 16), "r"(qs[0]), "r"(qs[1]), "r"(qs[2]), "r"(qs[3])
                     : "memory");
    }
}

// ---------------- weight prep: pad + convert + k-interleave ----------------
__global__ void prep_w(const float* __restrict__ w) {
    int idx = blockIdx.x * 256 + threadIdx.x;
    if (idx >= NPAIR * NOC * WROW) return;
    int kk = idx % WROW;
    int o  = (idx / WROW) % NOC;
    int p  = idx / (WROW * NOC);
    float v = 0.0f;
    if (kk < 112) {
        int i  = kk >> 1;          // feature index
        int ch = kk & 1;           // channel within pair
        if (i < 54) v = w[(o * NC + 2 * p + ch) * 54 + i];
    }
    g_W[idx] = __float2half(v);
}

// ---------------- main fused kernel ----------------
__global__ void __launch_bounds__(256, 1)
soc_fp16_kernel(const float* __restrict__ x, float* __restrict__ out) {
    extern __shared__ char smc[];
    const uint32_t smb = smem_u32(smc);
    const int tid  = threadIdx.x;
    const int wid  = tid >> 5;
    const int lane = tid & 31;

    const int bx = blockIdx.x;
    const int bb = bx / TILES_PER_IMG;
    const int t  = bx - bb * TILES_PER_IMG;
    const int th = t / NTW;
    const int h0 = th * 8;
    const int w0 = (t - th * NTW) * 32;
    const float* xb = x + (size_t)bb * NC * XCH;

    // warp tile: 64 oc x 64 pos
    const int m0 = (wid & 1) * 64;
    const int n0 = (wid >> 1) * 64;

    // featgen identity: 1 thread per position (tile 8 rows x 32 cols)
    const int pos = tid;
    const int prr = pos >> 5, pcc = pos & 31;

    int offv[9];
#pragma unroll
    for (int kh = 0; kh < 3; ++kh)
#pragma unroll
        for (int kw = 0; kw < 3; ++kw) {
            int gh = h0 + prr - 1 + kh;
            int gw = w0 + pcc - 1 + kw;
            offv[kh * 3 + kw] =
                ((unsigned)gh < IH && (unsigned)gw < IW) ? gh * IW + gw : -1;
        }

    // ---- prologue ----
    {   // cp.async W(0) -> buf0
        const char* src = (const char*)g_W;
#pragma unroll
        for (int i = 0; i < 8; ++i) {
            int e = tid + i * 256;
            if (e < W_CHUNKS) cpasync16(smb + SM_W0 + e * 16, src + e * 16);
        }
        asm volatile("cp.async.commit_group;");
    }
    __half2 t9[9];
#pragma unroll
    for (int j = 0; j < 9; ++j) {        // taps pair 0 (both channels packed)
        int o = offv[j];
        t9[j] = __floats2half2_rn((o >= 0) ? xb[o] : 0.0f,
                                  (o >= 0) ? xb[XCH + o] : 0.0f);
    }
    featgen_row(smb + SM_F0 + (uint32_t)(pos * FROWB), t9);
#pragma unroll
    for (int j = 0; j < 9; ++j) {        // taps pair 1
        int o = offv[j];
        t9[j] = __floats2half2_rn((o >= 0) ? xb[2 * XCH + o] : 0.0f,
                                  (o >= 0) ? xb[3 * XCH + o] : 0.0f);
    }
    asm volatile("cp.async.wait_group 0;" ::: "memory");
    __syncthreads();

    // lane-invariant ldmatrix offsets (relative to buffer base)
    const uint32_t aoff = (uint32_t)((m0 + (lane & 15)) * WROWB + (lane >> 4) * 16);
    // B (non-trans x4): lanes 0-7 m0(pos+0..7,k+0), 8-15 m1(pos,k+16),
    //                   16-23 m2(pos+8,k+0), 24-31 m3(pos+8,k+16)
    const uint32_t boff = (uint32_t)(n0 * FROWB + ((lane >> 4) & 1) * 8 * FROWB +
                                     ((lane >> 3) & 1) * 16 + (lane & 7) * FROWB);

    float acc[4][8][4];
#pragma unroll
    for (int i = 0; i < 4; ++i)
#pragma unroll
        for (int j = 0; j < 8; ++j)
#pragma unroll
            for (int k = 0; k < 4; ++k) acc[i][j][k] = 0.0f;

    // ---- main loop over channel pairs (one __syncthreads per pair) ----
    for (int p = 0; p < NPAIR; ++p) {
        const uint32_t wcur = smb + ((p & 1) ? SM_W1 : SM_W0);
        const uint32_t fcur = smb + ((p & 1) ? SM_F1 : SM_F0);
        const uint32_t fnxt = smb + ((p & 1) ? SM_F0 : SM_F1) + (uint32_t)(pos * FROWB);
        const bool notlast = (p < NPAIR - 1);

        // stage W(p+1) into the other W buffer (async; waited at loop bottom)
        if (notlast) {
            const char* src = (const char*)g_W + (size_t)(p + 1) * W_TILE_B;
            const uint32_t dst = smb + ((p & 1) ? SM_W0 : SM_W1);
#pragma unroll
            for (int i = 0; i < 8; ++i) {
                int e = tid + i * 256;
                if (e < W_CHUNKS) cpasync16(dst + e * 16, src + e * 16);
            }
            asm volatile("cp.async.commit_group;");
        }

        // MMA: 7 ksteps x (4 mtiles x 8 ntiles)
#pragma unroll
        for (int ks = 0; ks < 7; ++ks) {
            uint32_t ah[4][4], bq[4][4];
#pragma unroll
            for (int mt = 0; mt < 4; ++mt)
                ldsm_x4(ah[mt], wcur + aoff + (uint32_t)(mt * 16 * WROWB + ks * 32));
#pragma unroll
            for (int q = 0; q < 4; ++q)
                ldsm_x4(bq[q], fcur + boff + (uint32_t)(q * 16 * FROWB + ks * 32));
#pragma unroll
            for (int mt = 0; mt < 4; ++mt)
#pragma unroll
                for (int q = 0; q < 4; ++q) {
                    mma16816(acc[mt][2 * q],     ah[mt], &bq[q][0]);
                    mma16816(acc[mt][2 * q + 1], ah[mt], &bq[q][2]);
                }
        }

        if (notlast) {
            // featgen pair p+1 into the other F buffer (half2 math)
            featgen_row(fnxt, t9);

            // reload taps for pair p+2 (consumed a full pair later)
            if (p + 2 < NPAIR) {
                const float* xc = xb + (size_t)(2 * (p + 2)) * XCH;
#pragma unroll
                for (int j = 0; j < 9; ++j) {
                    int o = offv[j];
                    t9[j] = __floats2half2_rn((o >= 0) ? xc[o] : 0.0f,
                                              (o >= 0) ? xc[XCH + o] : 0.0f);
                }
            }
            asm volatile("cp.async.wait_group 0;" ::: "memory");
            __syncthreads();
        }
    }

    // ---- epilogue: direct register -> global float2 stores ----
    const int l4 = lane >> 2;
    const int l2 = (lane & 3) * 2;
#pragma unroll
    for (int mt = 0; mt < 4; ++mt) {
#pragma unroll
        for (int nt = 0; nt < 8; ++nt) {
            int oc = m0 + 16 * mt + l4;
            int pp = n0 + 8 * nt + l2;
            int hh = h0 + (pp >> 5);
            int ww = w0 + (pp & 31);
            float* p0 = out + (((size_t)(bb * NOC + oc) * IH + hh) * IW + ww);
            *(float2*)p0 = make_float2(acc[mt][nt][0], acc[mt][nt][1]);
            *(float2*)(p0 + (size_t)8 * IH * IW) =
                make_float2(acc[mt][nt][2], acc[mt][nt][3]);  // oc + 8
        }
    }
}

extern "C" void kernel_launch(void* const* d_in, const int* in_sizes, int n_in,
                              void* d_out, int out_size) {
    const float* x = (const float*)d_in[0];  // [8, 64, 96, 96]
    const float* w = (const float*)d_in[1];  // [128, 64, 54, 1]
    float* out = (float*)d_out;              // [8, 128, 96, 96]
    (void)in_sizes; (void)n_in; (void)out_size;

    cudaFuncSetAttribute(soc_fp16_kernel,
                         cudaFuncAttributeMaxDynamicSharedMemorySize, SM_TOTAL);

    prep_w<<<(NPAIR * NOC * WROW + 255) / 256, 256>>>(w);
    soc_fp16_kernel<<<NB * TILES_PER_IMG, 256, SM_TOTAL>>>(x, out);
}

// round 14
// speedup vs baseline: 1.2619x; 1.0580x over previous
#include <cuda_runtime.h>
#include <cuda_fp16.h>
#include <cstdint>

// Second-order conv2d as fused fp16 implicit GEMM on mma.sync (HMMA).
// CTA 128 oc x 256 pos, 8 warps (64x64), occ 1, W+F double-buffered, one
// __syncthreads per channel-pair. F stored [pos][k], k-interleaved
// (k=2i -> feature i of ch a, k=2i+1 -> ch b). Featgen = half2 chunks
// (4 HMUL2 + st.v4) interleaved 2-per-kstep inside the MMA loop; taps
// loaded raw at loop bottom, packed at kstep 0 of the next pair.

#define NB 8
#define NC 64
#define NOC 128
#define IH 96
#define IW 96
#define XCH (IH * IW)
#define NTW 3                   // 96 / 32
#define TILES_PER_IMG 36        // 12 x 3
#define NPAIR 32
#define WROWB 240               // bytes per W oc-row (120 fp16; 112 k + 8 pad)
#define FROWB 240               // bytes per F pos-row

// ---- SMEM layout (bytes) ----
#define SM_W0 0                          // 128*240 = 30720
#define SM_W1 30720
#define SM_F0 61440                      // 256*240 = 61440
#define SM_F1 122880
#define SM_TOTAL 184320

#define W_TILE_B 30720
#define W_CHUNKS (W_TILE_B / 16)         // 1920
#define WROW 120

// Pre-padded fp16 weights, k-interleaved: [pair][128 oc][120].
__device__ __align__(16) __half g_W[NPAIR * NOC * WROW];

// ---------------- helpers ----------------
__device__ __forceinline__ uint32_t smem_u32(const void* p) {
    uint32_t a;
    asm("{ .reg .u64 t; cvta.to.shared.u64 t, %1; cvt.u32.u64 %0, t; }" : "=r"(a) : "l"(p));
    return a;
}

__device__ __forceinline__ void ldsm_x4(uint32_t* r, uint32_t addr) {
    asm volatile("ldmatrix.sync.aligned.m8n8.x4.shared.b16 {%0,%1,%2,%3}, [%4];"
                 : "=r"(r[0]), "=r"(r[1]), "=r"(r[2]), "=r"(r[3]) : "r"(addr));
}

__device__ __forceinline__ void mma16816(float* d, const uint32_t* a, const uint32_t* b) {
    asm volatile(
        "mma.sync.aligned.m16n8k16.row.col.f32.f16.f16.f32 "
        "{%0,%1,%2,%3}, {%4,%5,%6,%7}, {%8,%9}, {%0,%1,%2,%3};"
        : "+f"(d[0]), "+f"(d[1]), "+f"(d[2]), "+f"(d[3])
        : "r"(a[0]), "r"(a[1]), "r"(a[2]), "r"(a[3]), "r"(b[0]), "r"(b[1]));
}

__device__ __forceinline__ void cpasync16(uint32_t dst, const void* src) {
    asm volatile("cp.async.cg.shared.global [%0], [%1], 16;" :: "r"(dst), "l"(src));
}

// cross-product index pair for cross feature r (0..35): (base, base+off)
__device__ __forceinline__ void cross_idx(int r, int& base, int& off) {
    if      (r <  8) { off = 1; base = r; }
    else if (r < 15) { off = 2; base = r - 8; }
    else if (r < 21) { off = 3; base = r - 15; }
    else if (r < 26) { off = 4; base = r - 21; }
    else if (r < 30) { off = 5; base = r - 26; }
    else if (r < 33) { off = 6; base = r - 30; }
    else if (r < 35) { off = 7; base = r - 33; }
    else             { off = 8; base = 0; }
}

// feature i (0..55, both channels packed in half2); folds under full unroll
__device__ __forceinline__ __half2 featval_h2(const __half2* t9, int i) {
    if (i < 9)  return t9[i];
    if (i < 18) return __hmul2(t9[i - 9], t9[i - 9]);
    if (i < 54) {
        int base, off;
        cross_idx(i - 18, base, off);
        return __hmul2(t9[base], t9[base + off]);
    }
    return __floats2half2_rn(0.f, 0.f);
}

// one 16B feature chunk (half2 features 4c..4c+3) -> volatile st.v4
__device__ __forceinline__ void fchunk(uint32_t dst, const __half2* t9, int c) {
    uint32_t qs[4];
#pragma unroll
    for (int h = 0; h < 4; ++h) {
        __half2 r = featval_h2(t9, c * 4 + h);
        qs[h] = *(uint32_t*)&r;
    }
    asm volatile("st.shared.v4.b32 [%0], {%1,%2,%3,%4};"
                 :: "r"(dst + c * 16), "r"(qs[0]), "r"(qs[1]), "r"(qs[2]), "r"(qs[3])
                 : "memory");
}

// ---------------- weight prep: pad + convert + k-interleave ----------------
__global__ void prep_w(const float* __restrict__ w) {
    int idx = blockIdx.x * 256 + threadIdx.x;
    if (idx >= NPAIR * NOC * WROW) return;
    int kk = idx % WROW;
    int o  = (idx / WROW) % NOC;
    int p  = idx / (WROW * NOC);
    float v = 0.0f;
    if (kk < 112) {
        int i  = kk >> 1;          // feature index
        int ch = kk & 1;           // channel within pair
        if (i < 54) v = w[(o * NC + 2 * p + ch) * 54 + i];
    }
    g_W[idx] = __float2half(v);
}

// ---------------- main fused kernel ----------------
__global__ void __launch_bounds__(256, 1)
soc_fp16_kernel(const float* __restrict__ x, float* __restrict__ out) {
    extern __shared__ char smc[];
    const uint32_t smb = smem_u32(smc);
    const int tid  = threadIdx.x;
    const int wid  = tid >> 5;
    const int lane = tid & 31;

    const int bx = blockIdx.x;
    const int bb = bx / TILES_PER_IMG;
    const int t  = bx - bb * TILES_PER_IMG;
    const int th = t / NTW;
    const int h0 = th * 8;
    const int w0 = (t - th * NTW) * 32;
    const float* xb = x + (size_t)bb * NC * XCH;

    // warp tile: 64 oc x 64 pos
    const int m0 = (wid & 1) * 64;
    const int n0 = (wid >> 1) * 64;

    // featgen identity: 1 thread per position (tile 8 rows x 32 cols)
    const int pos = tid;
    const int prr = pos >> 5, pcc = pos & 31;

    int offv[9];
#pragma unroll
    for (int kh = 0; kh < 3; ++kh)
#pragma unroll
        for (int kw = 0; kw < 3; ++kw) {
            int gh = h0 + prr - 1 + kh;
            int gw = w0 + pcc - 1 + kw;
            offv[kh * 3 + kw] =
                ((unsigned)gh < IH && (unsigned)gw < IW) ? gh * IW + gw : -1;
        }

    // ---- prologue ----
    {   // cp.async W(0) -> buf0
        const char* src = (const char*)g_W;
#pragma unroll
        for (int i = 0; i < 8; ++i) {
            int e = tid + i * 256;
            if (e < W_CHUNKS) cpasync16(smb + SM_W0 + e * 16, src + e * 16);
        }
        asm volatile("cp.async.commit_group;");
    }
    float tfa[9], tfb[9];          // raw taps (no packs until consumption)
    __half2 t9[9];                 // packed taps for the pair being featgen'd
#pragma unroll
    for (int j = 0; j < 9; ++j) {  // taps pair 0
        int o = offv[j];
        tfa[j] = (o >= 0) ? xb[o] : 0.0f;
        tfb[j] = (o >= 0) ? xb[XCH + o] : 0.0f;
    }
#pragma unroll
    for (int j = 0; j < 9; ++j) t9[j] = __floats2half2_rn(tfa[j], tfb[j]);
    {   // featgen pair 0 -> F0 (prologue: not interleaved)
        const uint32_t f0 = smb + SM_F0 + (uint32_t)(pos * FROWB);
#pragma unroll
        for (int c = 0; c < 14; ++c) fchunk(f0, t9, c);
    }
#pragma unroll
    for (int j = 0; j < 9; ++j) {  // taps pair 1 (raw; packed at kstep 0 of p=0)
        int o = offv[j];
        tfa[j] = (o >= 0) ? xb[2 * XCH + o] : 0.0f;
        tfb[j] = (o >= 0) ? xb[3 * XCH + o] : 0.0f;
    }
    asm volatile("cp.async.wait_group 0;" ::: "memory");
    __syncthreads();

    // lane-invariant ldmatrix offsets (relative to buffer base)
    const uint32_t aoff = (uint32_t)((m0 + (lane & 15)) * WROWB + (lane >> 4) * 16);
    // B (non-trans x4): lanes 0-7 m0(pos+0..7,k+0), 8-15 m1(pos,k+16),
    //                   16-23 m2(pos+8,k+0), 24-31 m3(pos+8,k+16)
    const uint32_t boff = (uint32_t)(n0 * FROWB + ((lane >> 4) & 1) * 8 * FROWB +
                                     ((lane >> 3) & 1) * 16 + (lane & 7) * FROWB);

    float acc[4][8][4];
#pragma unroll
    for (int i = 0; i < 4; ++i)
#pragma unroll
        for (int j = 0; j < 8; ++j)
#pragma unroll
            for (int k = 0; k < 4; ++k) acc[i][j][k] = 0.0f;

    // ---- main loop over channel pairs (one __syncthreads per pair) ----
    for (int p = 0; p < NPAIR; ++p) {
        const uint32_t wcur = smb + ((p & 1) ? SM_W1 : SM_W0);
        const uint32_t fcur = smb + ((p & 1) ? SM_F1 : SM_F0);
        const uint32_t fnxt = smb + ((p & 1) ? SM_F0 : SM_F1) + (uint32_t)(pos * FROWB);
        const bool notlast = (p < NPAIR - 1);

        // stage W(p+1) into the other W buffer (async; waited at loop bottom)
        if (notlast) {
            const char* src = (const char*)g_W + (size_t)(p + 1) * W_TILE_B;
            const uint32_t dst = smb + ((p & 1) ? SM_W0 : SM_W1);
#pragma unroll
            for (int i = 0; i < 8; ++i) {
                int e = tid + i * 256;
                if (e < W_CHUNKS) cpasync16(dst + e * 16, src + e * 16);
            }
            asm volatile("cp.async.commit_group;");
        }

        // MMA: 7 ksteps x (4 mtiles x 8 ntiles); featgen(p+1) interleaved:
        // kstep 0: pack taps; ksteps 1..6: 2 chunks each; 2 tail chunks after.
#pragma unroll
        for (int ks = 0; ks < 7; ++ks) {
            uint32_t ah[4][4], bq[4][4];
#pragma unroll
            for (int mt = 0; mt < 4; ++mt)
                ldsm_x4(ah[mt], wcur + aoff + (uint32_t)(mt * 16 * WROWB + ks * 32));
#pragma unroll
            for (int q = 0; q < 4; ++q)
                ldsm_x4(bq[q], fcur + boff + (uint32_t)(q * 16 * FROWB + ks * 32));

            // first half of the MMAs
#pragma unroll
            for (int mt = 0; mt < 2; ++mt)
#pragma unroll
                for (int q = 0; q < 4; ++q) {
                    mma16816(acc[mt][2 * q],     ah[mt], &bq[q][0]);
                    mma16816(acc[mt][2 * q + 1], ah[mt], &bq[q][2]);
                }
            if (notlast) {
                if (ks == 0) {
#pragma unroll
                    for (int j = 0; j < 9; ++j)
                        t9[j] = __floats2half2_rn(tfa[j], tfb[j]);
                } else {
                    fchunk(fnxt, t9, 2 * (ks - 1));
                }
            }

            // second half of the MMAs
#pragma unroll
            for (int mt = 2; mt < 4; ++mt)
#pragma unroll
                for (int q = 0; q < 4; ++q) {
                    mma16816(acc[mt][2 * q],     ah[mt], &bq[q][0]);
                    mma16816(acc[mt][2 * q + 1], ah[mt], &bq[q][2]);
                }
            if (notlast && ks >= 1) fchunk(fnxt, t9, 2 * (ks - 1) + 1);
        }

        if (notlast) {
            // tail chunks 12, 13
            fchunk(fnxt, t9, 12);
            fchunk(fnxt, t9, 13);

            // reload taps for pair p+2 (raw; consumed at kstep 0 next pair)
            if (p + 2 < NPAIR) {
                const float* xc = xb + (size_t)(2 * (p + 2)) * XCH;
#pragma unroll
                for (int j = 0; j < 9; ++j) {
                    int o = offv[j];
                    tfa[j] = (o >= 0) ? xc[o] : 0.0f;
                    tfb[j] = (o >= 0) ? xc[XCH + o] : 0.0f;
                }
            }
            asm volatile("cp.async.wait_group 0;" ::: "memory");
            __syncthreads();
        }
    }

    // ---- epilogue: direct register -> global float2 stores ----
    const int l4 = lane >> 2;
    const int l2 = (lane & 3) * 2;
#pragma unroll
    for (int mt = 0; mt < 4; ++mt) {
#pragma unroll
        for (int nt = 0; nt < 8; ++nt) {
            int oc = m0 + 16 * mt + l4;
            int pp = n0 + 8 * nt + l2;
            int hh = h0 + (pp >> 5);
            int ww = w0 + (pp & 31);
            float* p0 = out + (((size_t)(bb * NOC + oc) * IH + hh) * IW + ww);
            *(float2*)p0 = make_float2(acc[mt][nt][0], acc[mt][nt][1]);
            *(float2*)(p0 + (size_t)8 * IH * IW) =
                make_float2(acc[mt][nt][2], acc[mt][nt][3]);  // oc + 8
        }
    }
}

extern "C" void kernel_launch(void* const* d_in, const int* in_sizes, int n_in,
                              void* d_out, int out_size) {
    const float* x = (const float*)d_in[0];  // [8, 64, 96, 96]
    const float* w = (const float*)d_in[1];  // [128, 64, 54, 1]
    float* out = (float*)d_out;              // [8, 128, 96, 96]
    (void)in_sizes; (void)n_in; (void)out_size;

    cudaFuncSetAttribute(soc_fp16_kernel,
                         cudaFuncAttributeMaxDynamicSharedMemorySize, SM_TOTAL);

    prep_w<<<(NPAIR * NOC * WROW + 255) / 256, 256>>>(w);
    soc_fp16_kernel<<<NB * TILES_PER_IMG, 256, SM_TOTAL>>>(x, out);
}